// round 10
// baseline (speedup 1.0000x reference)
#include <cuda_runtime.h>
#include <math_constants.h>

// Fused multi-scale maxpool + tile + add + relu.
// R10 = R7 (warp-autonomous, lane-contiguous nL=4 LDG.128s, shuffle window
// reduction, batch-4 tree loads, 64 regs, launch_bounds(128,8)) with the
// pool sections REORDERED p1 -> p2 -> p3 -> p4: the 12 fully-independent
// p1/p2 loads issue first, maximizing in-flight diversity while the deep
// p4/p3 batched chains run. Traffic, mapping, and register budget unchanged.

__device__ __forceinline__ float4 fmax4(const float4 a, const float4 b) {
    float4 r;
    r.x = fmaxf(a.x, b.x); r.y = fmaxf(a.y, b.y);
    r.z = fmaxf(a.z, b.z); r.w = fmaxf(a.w, b.w);
    return r;
}

__global__ __launch_bounds__(128, 8)
void fused_ffblock_kernel(
    const float* __restrict__ in1,   // [8,256, 64, 64]   k=2
    const float* __restrict__ in2,   // [8,128,128,128]   k=4
    const float* __restrict__ in3,   // [8, 64,256,256]   k=8
    const float* __restrict__ in4,   // [8, 32,512,512]   k=16
    const float* __restrict__ ff,    // [8,512, 32, 32]
    float* __restrict__ out)         // [8,512, 32, 32]
{
    const int lane = threadIdx.x & 31;
    const int warp = threadIdx.x >> 5;               // 0..3
    const int y  = blockIdx.x * 4 + warp;            // 0..31 pooled row
    const int cb = blockIdx.y;                       // 0..31 base channel
    const int b  = blockIdx.z;                       // 0..7
    const unsigned FULL = 0xffffffffu;

    // ================= p1: k=2, channels cb+32*{0..7} =================
    // 8 fully independent single LDG.128s — issued first for MLP diversity.
    float p1v[8];
    #pragma unroll
    for (int j = 0; j < 8; j++) {
        const int c = cb + 32 * j;
        const float* p = in1 + ((size_t)(b * 256 + c) * 4096) + (size_t)y * 128
                             + lane * 4;
        float4 v = *reinterpret_cast<const float4*>(p);
        float m0 = fmaxf(v.x, v.y);   // window 2*(lane&15), this row's part
        float m1 = fmaxf(v.z, v.w);   // window 2*(lane&15)+1
        m0 = fmaxf(m0, __shfl_xor_sync(FULL, m0, 16));  // combine rows 2y,2y+1
        m1 = fmaxf(m1, __shfl_xor_sync(FULL, m1, 16));
        float w0 = __shfl_sync(FULL, m0, lane >> 1);
        float w1 = __shfl_sync(FULL, m1, lane >> 1);
        p1v[j] = (lane & 1) ? w1 : w0;
    }

    // ================= p2: k=4, channels cb+32*{0..3} =================
    float p2v[4];
    #pragma unroll
    for (int j = 0; j < 4; j++) {
        const int c = cb + 32 * j;
        const float* p = in2 + (((size_t)(b * 128 + c) * 128 + (size_t)y * 4) * 128)
                             + lane * 4;
        float4 v0 = *reinterpret_cast<const float4*>(p);
        float4 v1 = *reinterpret_cast<const float4*>(p + 128);
        float4 v2 = *reinterpret_cast<const float4*>(p + 256);
        float4 v3 = *reinterpret_cast<const float4*>(p + 384);
        float4 a = fmax4(fmax4(v0, v1), fmax4(v2, v3));
        p2v[j] = fmaxf(fmaxf(a.x, a.y), fmaxf(a.z, a.w));
    }

    // ================= p3: k=8, channels cb, cb+32 =================
    float p3v[2];
    #pragma unroll
    for (int j = 0; j < 2; j++) {
        const int c = cb + 32 * j;
        const float* base = in3 + (((size_t)(b * 64 + c) * 256 + (size_t)y * 8) * 256);
        float m3g[2];
        #pragma unroll
        for (int xg = 0; xg < 2; xg++) {
            const float* p = base + xg * 128 + lane * 4;
            float4 acc;
            #pragma unroll
            for (int r = 0; r < 8; r += 4) {
                float4 v0 = *reinterpret_cast<const float4*>(p + (size_t)(r + 0) * 256);
                float4 v1 = *reinterpret_cast<const float4*>(p + (size_t)(r + 1) * 256);
                float4 v2 = *reinterpret_cast<const float4*>(p + (size_t)(r + 2) * 256);
                float4 v3 = *reinterpret_cast<const float4*>(p + (size_t)(r + 3) * 256);
                float4 t = fmax4(fmax4(v0, v1), fmax4(v2, v3));
                acc = (r == 0) ? t : fmax4(acc, t);
            }
            float m = fmaxf(fmaxf(acc.x, acc.y), fmaxf(acc.z, acc.w));
            m = fmaxf(m, __shfl_xor_sync(FULL, m, 1));
            m3g[xg] = m;   // pair (lane>>1) -> window xg*16 + (lane>>1)
        }
        const int src = (lane & 15) << 1;
        float w0 = __shfl_sync(FULL, m3g[0], src);
        float w1 = __shfl_sync(FULL, m3g[1], src);
        p3v[j] = (lane < 16) ? w0 : w1;
    }

    // ================= p4: k=16, channel cb =================
    float m4g[4];
    {
        const float* base = in4 + (((size_t)(b * 32 + cb) * 512 + (size_t)y * 16) * 512);
        #pragma unroll
        for (int xg = 0; xg < 4; xg++) {
            const float* p = base + xg * 128 + lane * 4;
            float4 acc;
            #pragma unroll
            for (int r = 0; r < 16; r += 4) {
                // 4 independent loads in flight before any max consumes them
                float4 v0 = *reinterpret_cast<const float4*>(p + (size_t)(r + 0) * 512);
                float4 v1 = *reinterpret_cast<const float4*>(p + (size_t)(r + 1) * 512);
                float4 v2 = *reinterpret_cast<const float4*>(p + (size_t)(r + 2) * 512);
                float4 v3 = *reinterpret_cast<const float4*>(p + (size_t)(r + 3) * 512);
                float4 t = fmax4(fmax4(v0, v1), fmax4(v2, v3));
                acc = (r == 0) ? t : fmax4(acc, t);
            }
            float m = fmaxf(fmaxf(acc.x, acc.y), fmaxf(acc.z, acc.w));
            m = fmaxf(m, __shfl_xor_sync(FULL, m, 1));
            m = fmaxf(m, __shfl_xor_sync(FULL, m, 2));
            m4g[xg] = m;   // group (lane>>2) -> window xg*8 + (lane>>2)
        }
    }
    float p4v;
    {
        const int src = (lane & 7) << 2;
        float w0 = __shfl_sync(FULL, m4g[0], src);
        float w1 = __shfl_sync(FULL, m4g[1], src);
        float w2 = __shfl_sync(FULL, m4g[2], src);
        float w3 = __shfl_sync(FULL, m4g[3], src);
        p4v = (lane < 16) ? ((lane < 8) ? w0 : w1) : ((lane < 24) ? w2 : w3);
    }

    // ================= combine: 16 output channels =================
    #pragma unroll
    for (int j = 0; j < 16; j++) {
        const size_t o = (((size_t)(b * 512 + cb + 32 * j)) * 32 + y) * 32 + lane;
        float s = p1v[j & 7] + p2v[j & 3] + p3v[j & 1] + p4v + ff[o];
        out[o] = fmaxf(s, 0.0f);
    }
}

extern "C" void kernel_launch(void* const* d_in, const int* in_sizes, int n_in,
                              void* d_out, int out_size) {
    const float* in1 = (const float*)d_in[0];
    const float* in2 = (const float*)d_in[1];
    const float* in3 = (const float*)d_in[2];
    const float* in4 = (const float*)d_in[3];
    const float* ff  = (const float*)d_in[4];
    float* out = (float*)d_out;

    dim3 block(128, 1, 1);    // 4 warps, each owns one pooled row
    dim3 grid(8, 32, 8);      // y-groups x cb x b = 2048 blocks

    fused_ffblock_kernel<<<grid, block>>>(in1, in2, in3, in4, ff, out);
}

// round 11
// speedup vs baseline: 1.0211x; 1.0211x over previous
#include <cuda_runtime.h>
#include <math_constants.h>

// Fused multi-scale maxpool + tile + add + relu. FINAL (= R7, measured best,
// reproduced twice: 86.4 and 86.1 us, DRAM 82.3-82.4%).
//
// Structure: warp-autonomous (one warp = one (b, cb, pooled row y)), all
// loads lane-contiguous 512B LDG.128s (nL=4, sector-minimal), window maxima
// via shuffles, no smem, no barriers. Every input byte read exactly once
// chip-wide (channel-tiling reuse folded into the 16-channel combine).
// p4/p3/p2 batch 4 independent float4 loads before any fmax (tree reduce):
// per-warp load batching, NOT occupancy, sets DRAM% on sm_103a
// (regs 40 -> 72%, 48 -> 80.7%, 64 -> 82.3%; batch-8/80 regs plateaus;
// occupancy fell 67% -> 44% while BW rose). Streaming hints (__ldcs/__stcs)
// regress code-gen (-10% BW) and are deliberately absent.
// 6.5 TB/s on a 553 MB once-through mixed stream = HBM-interface-bound floor.

__device__ __forceinline__ float4 fmax4(const float4 a, const float4 b) {
    float4 r;
    r.x = fmaxf(a.x, b.x); r.y = fmaxf(a.y, b.y);
    r.z = fmaxf(a.z, b.z); r.w = fmaxf(a.w, b.w);
    return r;
}

__global__ __launch_bounds__(128, 8)
void fused_ffblock_kernel(
    const float* __restrict__ in1,   // [8,256, 64, 64]   k=2
    const float* __restrict__ in2,   // [8,128,128,128]   k=4
    const float* __restrict__ in3,   // [8, 64,256,256]   k=8
    const float* __restrict__ in4,   // [8, 32,512,512]   k=16
    const float* __restrict__ ff,    // [8,512, 32, 32]
    float* __restrict__ out)         // [8,512, 32, 32]
{
    const int lane = threadIdx.x & 31;
    const int warp = threadIdx.x >> 5;               // 0..3
    const int y  = blockIdx.x * 4 + warp;            // 0..31 pooled row
    const int cb = blockIdx.y;                       // 0..31 base channel
    const int b  = blockIdx.z;                       // 0..7
    const unsigned FULL = 0xffffffffu;

    // ================= p4: k=16, channel cb =================
    float m4g[4];
    {
        const float* base = in4 + (((size_t)(b * 32 + cb) * 512 + (size_t)y * 16) * 512);
        #pragma unroll
        for (int xg = 0; xg < 4; xg++) {
            const float* p = base + xg * 128 + lane * 4;
            float4 acc;
            #pragma unroll
            for (int r = 0; r < 16; r += 4) {
                // 4 independent loads in flight before any max consumes them
                float4 v0 = *reinterpret_cast<const float4*>(p + (size_t)(r + 0) * 512);
                float4 v1 = *reinterpret_cast<const float4*>(p + (size_t)(r + 1) * 512);
                float4 v2 = *reinterpret_cast<const float4*>(p + (size_t)(r + 2) * 512);
                float4 v3 = *reinterpret_cast<const float4*>(p + (size_t)(r + 3) * 512);
                float4 t = fmax4(fmax4(v0, v1), fmax4(v2, v3));
                acc = (r == 0) ? t : fmax4(acc, t);
            }
            float m = fmaxf(fmaxf(acc.x, acc.y), fmaxf(acc.z, acc.w));
            m = fmaxf(m, __shfl_xor_sync(FULL, m, 1));
            m = fmaxf(m, __shfl_xor_sync(FULL, m, 2));
            m4g[xg] = m;   // group (lane>>2) -> window xg*8 + (lane>>2)
        }
    }
    float p4v;
    {
        const int src = (lane & 7) << 2;
        float w0 = __shfl_sync(FULL, m4g[0], src);
        float w1 = __shfl_sync(FULL, m4g[1], src);
        float w2 = __shfl_sync(FULL, m4g[2], src);
        float w3 = __shfl_sync(FULL, m4g[3], src);
        p4v = (lane < 16) ? ((lane < 8) ? w0 : w1) : ((lane < 24) ? w2 : w3);
    }

    // ================= p3: k=8, channels cb, cb+32 =================
    float p3v[2];
    #pragma unroll
    for (int j = 0; j < 2; j++) {
        const int c = cb + 32 * j;
        const float* base = in3 + (((size_t)(b * 64 + c) * 256 + (size_t)y * 8) * 256);
        float m3g[2];
        #pragma unroll
        for (int xg = 0; xg < 2; xg++) {
            const float* p = base + xg * 128 + lane * 4;
            float4 acc;
            #pragma unroll
            for (int r = 0; r < 8; r += 4) {
                float4 v0 = *reinterpret_cast<const float4*>(p + (size_t)(r + 0) * 256);
                float4 v1 = *reinterpret_cast<const float4*>(p + (size_t)(r + 1) * 256);
                float4 v2 = *reinterpret_cast<const float4*>(p + (size_t)(r + 2) * 256);
                float4 v3 = *reinterpret_cast<const float4*>(p + (size_t)(r + 3) * 256);
                float4 t = fmax4(fmax4(v0, v1), fmax4(v2, v3));
                acc = (r == 0) ? t : fmax4(acc, t);
            }
            float m = fmaxf(fmaxf(acc.x, acc.y), fmaxf(acc.z, acc.w));
            m = fmaxf(m, __shfl_xor_sync(FULL, m, 1));
            m3g[xg] = m;   // pair (lane>>1) -> window xg*16 + (lane>>1)
        }
        const int src = (lane & 15) << 1;
        float w0 = __shfl_sync(FULL, m3g[0], src);
        float w1 = __shfl_sync(FULL, m3g[1], src);
        p3v[j] = (lane < 16) ? w0 : w1;
    }

    // ================= p2: k=4, channels cb+32*{0..3} =================
    float p2v[4];
    #pragma unroll
    for (int j = 0; j < 4; j++) {
        const int c = cb + 32 * j;
        const float* p = in2 + (((size_t)(b * 128 + c) * 128 + (size_t)y * 4) * 128)
                             + lane * 4;
        float4 v0 = *reinterpret_cast<const float4*>(p);
        float4 v1 = *reinterpret_cast<const float4*>(p + 128);
        float4 v2 = *reinterpret_cast<const float4*>(p + 256);
        float4 v3 = *reinterpret_cast<const float4*>(p + 384);
        float4 a = fmax4(fmax4(v0, v1), fmax4(v2, v3));
        p2v[j] = fmaxf(fmaxf(a.x, a.y), fmaxf(a.z, a.w));
    }

    // ================= p1: k=2, channels cb+32*{0..7} =================
    float p1v[8];
    #pragma unroll
    for (int j = 0; j < 8; j++) {
        const int c = cb + 32 * j;
        const float* p = in1 + ((size_t)(b * 256 + c) * 4096) + (size_t)y * 128
                             + lane * 4;
        float4 v = *reinterpret_cast<const float4*>(p);
        float m0 = fmaxf(v.x, v.y);   // window 2*(lane&15), this row's part
        float m1 = fmaxf(v.z, v.w);   // window 2*(lane&15)+1
        m0 = fmaxf(m0, __shfl_xor_sync(FULL, m0, 16));  // combine rows 2y,2y+1
        m1 = fmaxf(m1, __shfl_xor_sync(FULL, m1, 16));
        float w0 = __shfl_sync(FULL, m0, lane >> 1);
        float w1 = __shfl_sync(FULL, m1, lane >> 1);
        p1v[j] = (lane & 1) ? w1 : w0;
    }

    // ================= combine: 16 output channels =================
    #pragma unroll
    for (int j = 0; j < 16; j++) {
        const size_t o = (((size_t)(b * 512 + cb + 32 * j)) * 32 + y) * 32 + lane;
        float s = p1v[j & 7] + p2v[j & 3] + p3v[j & 1] + p4v + ff[o];
        out[o] = fmaxf(s, 0.0f);
    }
}

extern "C" void kernel_launch(void* const* d_in, const int* in_sizes, int n_in,
                              void* d_out, int out_size) {
    const float* in1 = (const float*)d_in[0];
    const float* in2 = (const float*)d_in[1];
    const float* in3 = (const float*)d_in[2];
    const float* in4 = (const float*)d_in[3];
    const float* ff  = (const float*)d_in[4];
    float* out = (float*)d_out;

    dim3 block(128, 1, 1);    // 4 warps, each owns one pooled row
    dim3 grid(8, 32, 8);      // y-groups x cb x b = 2048 blocks

    fused_ffblock_kernel<<<grid, block>>>(in1, in2, in3, in4, ff, out);
}